// round 2
// baseline (speedup 1.0000x reference)
#include <cuda_runtime.h>
#include <cuda_bf16.h>
#include <math.h>

// Problem constants
#define NMAX 50000
#define EMAX 800000
#define HDIM 128
#define GCNT 128
#define CCNT 10

// ---------------- device scratch (no cudaMalloc allowed) ----------------
__device__ float g_h[NMAX * HDIM];     // GEMM output / agg input
__device__ float g_agg[NMAX * HDIM];   // aggregated features (next layer input)
__device__ float g_h3[NMAX * 16];      // layer-3 projected features (padded C)
__device__ float g_deg[NMAX];
__device__ float g_dinv[NMAX];
__device__ int   g_cnt[NMAX];
__device__ int   g_row[NMAX + 1];
__device__ int   g_cur[NMAX];
__device__ int   g_esrc[EMAX];
__device__ float g_ew2[EMAX];          // ew * dinv[src]
__device__ float g_psum[GCNT * CCNT];
__device__ float g_pcnt[GCNT];

// ---------------- preprocessing ----------------

__global__ void k_init(int n) {
    int i = blockIdx.x * blockDim.x + threadIdx.x;
    if (i < n) { g_deg[i] = 1.0f; g_cnt[i] = 0; }   // self-loop weight 1
    if (i < GCNT * CCNT) g_psum[i] = 0.0f;
    if (i < GCNT) g_pcnt[i] = 0.0f;
}

__global__ void k_count(const int* __restrict__ dst, const float* __restrict__ ew, int e) {
    int i = blockIdx.x * blockDim.x + threadIdx.x;
    if (i >= e) return;
    int d = dst[i];
    atomicAdd(&g_deg[d], ew[i]);
    atomicAdd(&g_cnt[d], 1);
}

__global__ void k_dinv(int n) {
    int i = blockIdx.x * blockDim.x + threadIdx.x;
    if (i >= n) return;
    float d = g_deg[i];
    g_dinv[i] = (d > 0.0f) ? rsqrtf(d) : 0.0f;
}

// single-block exclusive scan over g_cnt -> g_row, g_cur
__global__ void k_scan(int n) {
    __shared__ int sdata[1024];
    int tid = threadIdx.x;
    int chunk = (n + 1023) >> 10;
    int start = tid * chunk;
    int end = min(start + chunk, n);
    int local = 0;
    for (int i = start; i < end; i++) local += g_cnt[i];
    sdata[tid] = local;
    __syncthreads();
    // Hillis-Steele inclusive scan
    for (int off = 1; off < 1024; off <<= 1) {
        int v = (tid >= off) ? sdata[tid - off] : 0;
        __syncthreads();
        sdata[tid] += v;
        __syncthreads();
    }
    int run = sdata[tid] - local;   // exclusive base
    for (int i = start; i < end; i++) {
        g_row[i] = run;
        g_cur[i] = run;
        run += g_cnt[i];
    }
    if (tid == 1023) g_row[n] = sdata[1023];
}

__global__ void k_scatter(const int* __restrict__ src, const int* __restrict__ dst,
                          const float* __restrict__ ew, int e) {
    int i = blockIdx.x * blockDim.x + threadIdx.x;
    if (i >= e) return;
    int s = src[i], d = dst[i];
    int pos = atomicAdd(&g_cur[d], 1);
    g_esrc[pos] = s;
    g_ew2[pos] = ew[i] * g_dinv[s];
}

// ---------------- dense GEMM: [M,128] @ [128,128] -> [M,128] ----------------
// BM=128 BN=128 BK=8 TM=8 TN=8, 256 threads
__global__ __launch_bounds__(256, 2)
void sgemm128(const float* __restrict__ A, const float* __restrict__ B,
              float* __restrict__ C, int M) {
    __shared__ float As[8][128];   // [k][m]
    __shared__ float Bs[8][128];   // [k][n]
    int tid = threadIdx.x;
    int rowBase = blockIdx.x * 128;

    int aRow = tid >> 1;            // 0..127
    int aCol = (tid & 1) * 4;       // 0 or 4
    int bRow = tid >> 5;            // 0..7
    int bCol = (tid & 31) * 4;      // 0..124

    int tRow = (tid >> 4) * 8;      // 0..120
    int tCol = (tid & 15) * 8;      // 0..120

    float acc[8][8];
#pragma unroll
    for (int m = 0; m < 8; m++)
#pragma unroll
        for (int nn = 0; nn < 8; nn++) acc[m][nn] = 0.0f;

    for (int k0 = 0; k0 < 128; k0 += 8) {
        float4 av = make_float4(0.f, 0.f, 0.f, 0.f);
        int gr = rowBase + aRow;
        if (gr < M) av = *(const float4*)(A + gr * 128 + k0 + aCol);
        As[aCol + 0][aRow] = av.x;
        As[aCol + 1][aRow] = av.y;
        As[aCol + 2][aRow] = av.z;
        As[aCol + 3][aRow] = av.w;
        float4 bv = *(const float4*)(B + (k0 + bRow) * 128 + bCol);
        *(float4*)(&Bs[bRow][bCol]) = bv;
        __syncthreads();
#pragma unroll
        for (int k = 0; k < 8; k++) {
            float4 a0 = *(float4*)&As[k][tRow];
            float4 a1 = *(float4*)&As[k][tRow + 4];
            float4 b0 = *(float4*)&Bs[k][tCol];
            float4 b1 = *(float4*)&Bs[k][tCol + 4];
            float rm[8] = {a0.x, a0.y, a0.z, a0.w, a1.x, a1.y, a1.z, a1.w};
            float rn[8] = {b0.x, b0.y, b0.z, b0.w, b1.x, b1.y, b1.z, b1.w};
#pragma unroll
            for (int m = 0; m < 8; m++)
#pragma unroll
                for (int nn = 0; nn < 8; nn++)
                    acc[m][nn] = fmaf(rm[m], rn[nn], acc[m][nn]);
        }
        __syncthreads();
    }

#pragma unroll
    for (int m = 0; m < 8; m++) {
        int gr = rowBase + tRow + m;
        if (gr < M) {
            *(float4*)(C + gr * 128 + tCol)     = make_float4(acc[m][0], acc[m][1], acc[m][2], acc[m][3]);
            *(float4*)(C + gr * 128 + tCol + 4) = make_float4(acc[m][4], acc[m][5], acc[m][6], acc[m][7]);
        }
    }
}

// ---------------- aggregation: out[i] = dinv[i]*(sum_e w'_e h[src] + dinv[i] h[i]) + b ----------------
// one warp per node, 4 floats/lane (H=128)
__global__ __launch_bounds__(256)
void agg_h128(const float* __restrict__ h, float* __restrict__ out,
              const float* __restrict__ bias, int do_relu, int n) {
    int gw = (blockIdx.x * blockDim.x + threadIdx.x) >> 5;
    if (gw >= n) return;
    int lane = threadIdx.x & 31;
    const float4* h4 = (const float4*)h;

    float di = g_dinv[gw];
    float4 acc = h4[gw * 32 + lane];
    acc.x *= di; acc.y *= di; acc.z *= di; acc.w *= di;   // self-loop (×di again at end)

    int j = g_row[gw];
    int end = g_row[gw + 1];
    for (; j + 4 <= end; j += 4) {
        int s0 = g_esrc[j], s1 = g_esrc[j + 1], s2 = g_esrc[j + 2], s3 = g_esrc[j + 3];
        float w0 = g_ew2[j], w1 = g_ew2[j + 1], w2 = g_ew2[j + 2], w3 = g_ew2[j + 3];
        float4 v0 = h4[s0 * 32 + lane];
        float4 v1 = h4[s1 * 32 + lane];
        float4 v2 = h4[s2 * 32 + lane];
        float4 v3 = h4[s3 * 32 + lane];
        acc.x = fmaf(w0, v0.x, acc.x); acc.y = fmaf(w0, v0.y, acc.y);
        acc.z = fmaf(w0, v0.z, acc.z); acc.w = fmaf(w0, v0.w, acc.w);
        acc.x = fmaf(w1, v1.x, acc.x); acc.y = fmaf(w1, v1.y, acc.y);
        acc.z = fmaf(w1, v1.z, acc.z); acc.w = fmaf(w1, v1.w, acc.w);
        acc.x = fmaf(w2, v2.x, acc.x); acc.y = fmaf(w2, v2.y, acc.y);
        acc.z = fmaf(w2, v2.z, acc.z); acc.w = fmaf(w2, v2.w, acc.w);
        acc.x = fmaf(w3, v3.x, acc.x); acc.y = fmaf(w3, v3.y, acc.y);
        acc.z = fmaf(w3, v3.z, acc.z); acc.w = fmaf(w3, v3.w, acc.w);
    }
    for (; j < end; j++) {
        int s = g_esrc[j];
        float w = g_ew2[j];
        float4 v = h4[s * 32 + lane];
        acc.x = fmaf(w, v.x, acc.x); acc.y = fmaf(w, v.y, acc.y);
        acc.z = fmaf(w, v.z, acc.z); acc.w = fmaf(w, v.w, acc.w);
    }

    float4 bb = ((const float4*)bias)[lane];
    acc.x = fmaf(acc.x, di, bb.x);
    acc.y = fmaf(acc.y, di, bb.y);
    acc.z = fmaf(acc.z, di, bb.z);
    acc.w = fmaf(acc.w, di, bb.w);
    if (do_relu) {
        acc.x = fmaxf(acc.x, 0.f); acc.y = fmaxf(acc.y, 0.f);
        acc.z = fmaxf(acc.z, 0.f); acc.w = fmaxf(acc.w, 0.f);
    }
    ((float4*)out)[gw * 32 + lane] = acc;
}

// ---------------- layer 3 projection: [M,128] @ [128,10] -> [M,16] padded ----------------
// 32 rows per block, 512 threads = 32 rows x 16 cols
__global__ __launch_bounds__(512)
void gemm_w3(const float* __restrict__ A, const float* __restrict__ W, int M) {
    __shared__ float xs[32][128];
    __shared__ float Ws[128 * CCNT];
    int tid = threadIdx.x;
    int r0 = blockIdx.x * 32;

    for (int t = tid; t < 1024; t += 512) {
        int r = t >> 5;
        int c4 = (t & 31) << 2;
        int grow = r0 + r;
        float4 v = make_float4(0.f, 0.f, 0.f, 0.f);
        if (grow < M) v = *(const float4*)(A + grow * 128 + c4);
        *(float4*)&xs[r][c4] = v;
    }
    for (int t = tid; t < 128 * CCNT; t += 512) Ws[t] = W[t];
    __syncthreads();

    int r = tid >> 4;
    int c = tid & 15;
    if (c < CCNT) {
        float acc = 0.0f;
#pragma unroll
        for (int k = 0; k < 128; k++)
            acc = fmaf(xs[r][k], Ws[k * CCNT + c], acc);
        int grow = r0 + r;
        if (grow < M) g_h3[grow * 16 + c] = acc;
    }
}

// ---------------- layer 3 aggregation + global mean pool (fused) ----------------
// one warp per node; lanes 0..9 hold classes
__global__ __launch_bounds__(256)
void agg_c16_pool(const int* __restrict__ batch, const float* __restrict__ b3, int n) {
    int gw = (blockIdx.x * blockDim.x + threadIdx.x) >> 5;
    if (gw >= n) return;
    int lane = threadIdx.x & 31;
    bool active = (lane < CCNT);

    float di = g_dinv[gw];
    float acc = 0.0f;
    if (active) acc = g_h3[gw * 16 + lane] * di;

    int j = g_row[gw];
    int end = g_row[gw + 1];
    for (; j + 4 <= end; j += 4) {
        int s0 = g_esrc[j], s1 = g_esrc[j + 1], s2 = g_esrc[j + 2], s3 = g_esrc[j + 3];
        float w0 = g_ew2[j], w1 = g_ew2[j + 1], w2 = g_ew2[j + 2], w3 = g_ew2[j + 3];
        if (active) {
            acc = fmaf(w0, g_h3[s0 * 16 + lane], acc);
            acc = fmaf(w1, g_h3[s1 * 16 + lane], acc);
            acc = fmaf(w2, g_h3[s2 * 16 + lane], acc);
            acc = fmaf(w3, g_h3[s3 * 16 + lane], acc);
        }
    }
    for (; j < end; j++) {
        int s = g_esrc[j];
        float w = g_ew2[j];
        if (active) acc = fmaf(w, g_h3[s * 16 + lane], acc);
    }

    int g = batch[gw];
    if (active) {
        acc = fmaf(acc, di, b3[lane]);
        atomicAdd(&g_psum[g * CCNT + lane], acc);
    }
    if (lane == 0) atomicAdd(&g_pcnt[g], 1.0f);
}

// ---------------- final: mean + log_softmax ----------------
__global__ void k_finalize(float* __restrict__ out) {
    int g = threadIdx.x;   // 128 threads
    if (g >= GCNT) return;
    float c = fmaxf(g_pcnt[g], 1.0f);
    float v[CCNT];
    float m = -1e30f;
#pragma unroll
    for (int j = 0; j < CCNT; j++) {
        v[j] = g_psum[g * CCNT + j] / c;
        m = fmaxf(m, v[j]);
    }
    float s = 0.0f;
#pragma unroll
    for (int j = 0; j < CCNT; j++) s += expf(v[j] - m);
    float lse = logf(s) + m;
#pragma unroll
    for (int j = 0; j < CCNT; j++) out[g * CCNT + j] = v[j] - lse;
}

// ---------------- launch ----------------
extern "C" void kernel_launch(void* const* d_in, const int* in_sizes, int n_in,
                              void* d_out, int out_size) {
    const float* x    = (const float*)d_in[0];
    const int*   ei   = (const int*)d_in[1];
    const float* ea   = (const float*)d_in[2];
    const int*   bat  = (const int*)d_in[3];
    const float* W1   = (const float*)d_in[4];
    const float* b1   = (const float*)d_in[5];
    const float* W2   = (const float*)d_in[6];
    const float* b2   = (const float*)d_in[7];
    const float* W3   = (const float*)d_in[8];
    const float* b3   = (const float*)d_in[9];
    float* out = (float*)d_out;

    int n = in_sizes[0] / HDIM;   // 50000
    int e = in_sizes[1] / 2;      // 800000
    const int* src = ei;
    const int* dst = ei + e;

    float *gh, *gagg;
    cudaGetSymbolAddress((void**)&gh, g_h);
    cudaGetSymbolAddress((void**)&gagg, g_agg);

    // --- preprocessing: degrees + CSR-by-dst ---
    k_init<<<(n + 255) / 256, 256>>>(n);
    k_count<<<(e + 255) / 256, 256>>>(dst, ea, e);
    k_dinv<<<(n + 255) / 256, 256>>>(n);
    k_scan<<<1, 1024>>>(n);
    k_scatter<<<(e + 255) / 256, 256>>>(src, dst, ea, e);

    int gemmBlocks = (n + 127) / 128;
    int aggBlocks = (n * 32 + 255) / 256;

    // layer 1: h = x@W1 ; agg + b1 ; relu
    sgemm128<<<gemmBlocks, 256>>>(x, W1, gh, n);
    agg_h128<<<aggBlocks, 256>>>(gh, gagg, b1, 1, n);

    // layer 2
    sgemm128<<<gemmBlocks, 256>>>(gagg, W2, gh, n);
    agg_h128<<<aggBlocks, 256>>>(gh, gagg, b2, 1, n);

    // layer 3: project to C first (12.8x less edge traffic), then aggregate + pool
    gemm_w3<<<(n + 31) / 32, 512>>>(gagg, W3, n);
    agg_c16_pool<<<aggBlocks, 256>>>(bat, b3, n);

    k_finalize<<<1, 128>>>(out);
}

// round 3
// speedup vs baseline: 1.3048x; 1.3048x over previous
#include <cuda_runtime.h>
#include <cuda_bf16.h>
#include <math.h>

// Problem constants
#define NMAX 50000
#define EMAX 800000
#define HDIM 128
#define GCNT 128
#define CCNT 10
#define SCAN_BLK 512
#define NB_MAX ((NMAX + SCAN_BLK - 1) / SCAN_BLK)   // 98

// ---------------- device scratch (no cudaMalloc allowed) ----------------
__device__ float g_h[NMAX * HDIM];     // GEMM output / agg input
__device__ float g_agg[NMAX * HDIM];   // aggregated features (next layer input)
__device__ float g_h3[NMAX * 16];      // layer-3 projected features (padded C)
__device__ float g_deg[NMAX];
__device__ float g_dinv[NMAX];
__device__ int   g_cnt[NMAX];
__device__ int   g_row[NMAX + 1];
__device__ int   g_cur[NMAX];
__device__ int   g_bsum[128];
__device__ int   g_boff[128];
__device__ int   g_esrc[EMAX];
__device__ float g_ew2[EMAX];          // ew * dinv[src]
__device__ float g_psum[GCNT * CCNT];
__device__ float g_pcnt[GCNT];

// ---------------- preprocessing ----------------

__global__ void k_init(int n) {
    int i = blockIdx.x * blockDim.x + threadIdx.x;
    if (i < n) { g_deg[i] = 1.0f; g_cnt[i] = 0; }   // self-loop weight 1
    if (i < GCNT * CCNT) g_psum[i] = 0.0f;
    if (i < GCNT) g_pcnt[i] = 0.0f;
}

__global__ void k_count(const int* __restrict__ dst, const float* __restrict__ ew, int e) {
    int i = blockIdx.x * blockDim.x + threadIdx.x;
    if (i >= e) return;
    int d = dst[i];
    atomicAdd(&g_deg[d], ew[i]);
    atomicAdd(&g_cnt[d], 1);
}

__global__ void k_dinv(int n) {
    int i = blockIdx.x * blockDim.x + threadIdx.x;
    if (i >= n) return;
    float d = g_deg[i];
    g_dinv[i] = (d > 0.0f) ? rsqrtf(d) : 0.0f;
}

// ---- multi-block exclusive scan of g_cnt -> g_row (3 phases) ----

// phase 1: per-block exclusive scan (partial, no global offset) + block sums
__global__ void k_scan1(int n) {
    __shared__ int sd[SCAN_BLK];
    int tid = threadIdx.x;
    int i = blockIdx.x * SCAN_BLK + tid;
    int v = (i < n) ? g_cnt[i] : 0;
    sd[tid] = v;
    __syncthreads();
#pragma unroll
    for (int off = 1; off < SCAN_BLK; off <<= 1) {
        int t = (tid >= off) ? sd[tid - off] : 0;
        __syncthreads();
        sd[tid] += t;
        __syncthreads();
    }
    if (i < n) g_row[i] = sd[tid] - v;         // exclusive within block
    if (tid == SCAN_BLK - 1) g_bsum[blockIdx.x] = sd[SCAN_BLK - 1];
}

// phase 2: single small block scans the <=98 block sums
__global__ void k_scan2(int nb, int n, int e) {
    __shared__ int sd[128];
    int tid = threadIdx.x;   // 128 threads
    int v = (tid < nb) ? g_bsum[tid] : 0;
    sd[tid] = v;
    __syncthreads();
#pragma unroll
    for (int off = 1; off < 128; off <<= 1) {
        int t = (tid >= off) ? sd[tid - off] : 0;
        __syncthreads();
        sd[tid] += t;
        __syncthreads();
    }
    if (tid < nb) g_boff[tid] = sd[tid] - v;   // exclusive block offsets
    if (tid == 0) g_row[n] = e;                // total is always e
}

// phase 3: apply block offsets, mirror into g_cur
__global__ void k_scan3(int n) {
    int i = blockIdx.x * SCAN_BLK + threadIdx.x;
    if (i < n) {
        int r = g_row[i] + g_boff[blockIdx.x];
        g_row[i] = r;
        g_cur[i] = r;
    }
}

__global__ void k_scatter(const int* __restrict__ src, const int* __restrict__ dst,
                          const float* __restrict__ ew, int e) {
    int i = blockIdx.x * blockDim.x + threadIdx.x;
    if (i >= e) return;
    int s = src[i], d = dst[i];
    int pos = atomicAdd(&g_cur[d], 1);
    g_esrc[pos] = s;
    g_ew2[pos] = ew[i] * g_dinv[s];
}

// ---------------- dense GEMM: [M,128] @ [128,128] -> [M,128] ----------------
// BM=128 BN=128 BK=8 TM=8 TN=8, 256 threads, double-buffered smem
__global__ __launch_bounds__(256, 2)
void sgemm128(const float* __restrict__ A, const float* __restrict__ B,
              float* __restrict__ C, int M) {
    __shared__ float As[2][8][128];   // [buf][k][m]
    __shared__ float Bs[2][8][128];   // [buf][k][n]
    int tid = threadIdx.x;
    int rowBase = blockIdx.x * 128;

    int aRow = tid >> 1;            // 0..127
    int aCol = (tid & 1) * 4;       // 0 or 4
    int bRow = tid >> 5;            // 0..7
    int bCol = (tid & 31) * 4;      // 0..124

    int tRow = (tid >> 4) * 8;      // 0..120
    int tCol = (tid & 15) * 8;      // 0..120

    int gr = rowBase + aRow;
    bool aOk = (gr < M);
    const float4* Aptr = (const float4*)(A + (size_t)(aOk ? gr : 0) * 128 + aCol);

    float acc[8][8];
#pragma unroll
    for (int m = 0; m < 8; m++)
#pragma unroll
        for (int nn = 0; nn < 8; nn++) acc[m][nn] = 0.0f;

    // preload k0 = 0 into buffer 0
    {
        float4 av = make_float4(0.f, 0.f, 0.f, 0.f);
        if (aOk) av = Aptr[0];
        As[0][aCol + 0][aRow] = av.x;
        As[0][aCol + 1][aRow] = av.y;
        As[0][aCol + 2][aRow] = av.z;
        As[0][aCol + 3][aRow] = av.w;
        *(float4*)(&Bs[0][bRow][bCol]) = *(const float4*)(B + bRow * 128 + bCol);
    }
    __syncthreads();

    int p = 0;
    for (int k0 = 0; k0 < 128; k0 += 8) {
        bool more = (k0 + 8) < 128;
        float4 av2 = make_float4(0.f, 0.f, 0.f, 0.f);
        float4 bv2;
        if (more) {
            if (aOk) av2 = Aptr[(k0 + 8) >> 2];
            bv2 = *(const float4*)(B + (k0 + 8 + bRow) * 128 + bCol);
        }
#pragma unroll
        for (int k = 0; k < 8; k++) {
            float4 a0 = *(float4*)&As[p][k][tRow];
            float4 a1 = *(float4*)&As[p][k][tRow + 4];
            float4 b0 = *(float4*)&Bs[p][k][tCol];
            float4 b1 = *(float4*)&Bs[p][k][tCol + 4];
            float rm[8] = {a0.x, a0.y, a0.z, a0.w, a1.x, a1.y, a1.z, a1.w};
            float rn[8] = {b0.x, b0.y, b0.z, b0.w, b1.x, b1.y, b1.z, b1.w};
#pragma unroll
            for (int m = 0; m < 8; m++)
#pragma unroll
                for (int nn = 0; nn < 8; nn++)
                    acc[m][nn] = fmaf(rm[m], rn[nn], acc[m][nn]);
        }
        if (more) {
            int q = p ^ 1;
            As[q][aCol + 0][aRow] = av2.x;
            As[q][aCol + 1][aRow] = av2.y;
            As[q][aCol + 2][aRow] = av2.z;
            As[q][aCol + 3][aRow] = av2.w;
            *(float4*)(&Bs[q][bRow][bCol]) = bv2;
            __syncthreads();
            p = q;
        }
    }

#pragma unroll
    for (int m = 0; m < 8; m++) {
        int grr = rowBase + tRow + m;
        if (grr < M) {
            *(float4*)(C + (size_t)grr * 128 + tCol)     = make_float4(acc[m][0], acc[m][1], acc[m][2], acc[m][3]);
            *(float4*)(C + (size_t)grr * 128 + tCol + 4) = make_float4(acc[m][4], acc[m][5], acc[m][6], acc[m][7]);
        }
    }
}

// ---------------- aggregation: out[i] = dinv[i]*(sum_e w'_e h[src] + dinv[i] h[i]) + b ----------------
// one warp per node, 4 floats/lane (H=128)
__global__ __launch_bounds__(256)
void agg_h128(const float* __restrict__ h, float* __restrict__ out,
              const float* __restrict__ bias, int do_relu, int n) {
    int gw = (blockIdx.x * blockDim.x + threadIdx.x) >> 5;
    if (gw >= n) return;
    int lane = threadIdx.x & 31;
    const float4* h4 = (const float4*)h;

    float di = g_dinv[gw];
    float4 acc = h4[gw * 32 + lane];
    acc.x *= di; acc.y *= di; acc.z *= di; acc.w *= di;   // self-loop (×di again at end)

    int j = g_row[gw];
    int end = g_row[gw + 1];
    for (; j + 4 <= end; j += 4) {
        int s0 = g_esrc[j], s1 = g_esrc[j + 1], s2 = g_esrc[j + 2], s3 = g_esrc[j + 3];
        float w0 = g_ew2[j], w1 = g_ew2[j + 1], w2 = g_ew2[j + 2], w3 = g_ew2[j + 3];
        float4 v0 = h4[s0 * 32 + lane];
        float4 v1 = h4[s1 * 32 + lane];
        float4 v2 = h4[s2 * 32 + lane];
        float4 v3 = h4[s3 * 32 + lane];
        acc.x = fmaf(w0, v0.x, acc.x); acc.y = fmaf(w0, v0.y, acc.y);
        acc.z = fmaf(w0, v0.z, acc.z); acc.w = fmaf(w0, v0.w, acc.w);
        acc.x = fmaf(w1, v1.x, acc.x); acc.y = fmaf(w1, v1.y, acc.y);
        acc.z = fmaf(w1, v1.z, acc.z); acc.w = fmaf(w1, v1.w, acc.w);
        acc.x = fmaf(w2, v2.x, acc.x); acc.y = fmaf(w2, v2.y, acc.y);
        acc.z = fmaf(w2, v2.z, acc.z); acc.w = fmaf(w2, v2.w, acc.w);
        acc.x = fmaf(w3, v3.x, acc.x); acc.y = fmaf(w3, v3.y, acc.y);
        acc.z = fmaf(w3, v3.z, acc.z); acc.w = fmaf(w3, v3.w, acc.w);
    }
    for (; j < end; j++) {
        int s = g_esrc[j];
        float w = g_ew2[j];
        float4 v = h4[s * 32 + lane];
        acc.x = fmaf(w, v.x, acc.x); acc.y = fmaf(w, v.y, acc.y);
        acc.z = fmaf(w, v.z, acc.z); acc.w = fmaf(w, v.w, acc.w);
    }

    float4 bb = ((const float4*)bias)[lane];
    acc.x = fmaf(acc.x, di, bb.x);
    acc.y = fmaf(acc.y, di, bb.y);
    acc.z = fmaf(acc.z, di, bb.z);
    acc.w = fmaf(acc.w, di, bb.w);
    if (do_relu) {
        acc.x = fmaxf(acc.x, 0.f); acc.y = fmaxf(acc.y, 0.f);
        acc.z = fmaxf(acc.z, 0.f); acc.w = fmaxf(acc.w, 0.f);
    }
    ((float4*)out)[gw * 32 + lane] = acc;
}

// ---------------- layer 3 projection: [M,128] @ [128,10] -> [M,16] padded ----------------
__global__ __launch_bounds__(512)
void gemm_w3(const float* __restrict__ A, const float* __restrict__ W, int M) {
    __shared__ float xs[32][128];
    __shared__ float Ws[128 * CCNT];
    int tid = threadIdx.x;
    int r0 = blockIdx.x * 32;

    for (int t = tid; t < 1024; t += 512) {
        int r = t >> 5;
        int c4 = (t & 31) << 2;
        int grow = r0 + r;
        float4 v = make_float4(0.f, 0.f, 0.f, 0.f);
        if (grow < M) v = *(const float4*)(A + (size_t)grow * 128 + c4);
        *(float4*)&xs[r][c4] = v;
    }
    for (int t = tid; t < 128 * CCNT; t += 512) Ws[t] = W[t];
    __syncthreads();

    int r = tid >> 4;
    int c = tid & 15;
    if (c < CCNT) {
        float acc = 0.0f;
#pragma unroll
        for (int k = 0; k < 128; k++)
            acc = fmaf(xs[r][k], Ws[k * CCNT + c], acc);
        int grow = r0 + r;
        if (grow < M) g_h3[grow * 16 + c] = acc;
    }
}

// ---------------- layer 3 aggregation + global mean pool (fused) ----------------
__global__ __launch_bounds__(256)
void agg_c16_pool(const int* __restrict__ batch, const float* __restrict__ b3, int n) {
    int gw = (blockIdx.x * blockDim.x + threadIdx.x) >> 5;
    if (gw >= n) return;
    int lane = threadIdx.x & 31;
    bool active = (lane < CCNT);

    float di = g_dinv[gw];
    float acc = 0.0f;
    if (active) acc = g_h3[gw * 16 + lane] * di;

    int j = g_row[gw];
    int end = g_row[gw + 1];
    for (; j + 4 <= end; j += 4) {
        int s0 = g_esrc[j], s1 = g_esrc[j + 1], s2 = g_esrc[j + 2], s3 = g_esrc[j + 3];
        float w0 = g_ew2[j], w1 = g_ew2[j + 1], w2 = g_ew2[j + 2], w3 = g_ew2[j + 3];
        if (active) {
            acc = fmaf(w0, g_h3[s0 * 16 + lane], acc);
            acc = fmaf(w1, g_h3[s1 * 16 + lane], acc);
            acc = fmaf(w2, g_h3[s2 * 16 + lane], acc);
            acc = fmaf(w3, g_h3[s3 * 16 + lane], acc);
        }
    }
    for (; j < end; j++) {
        int s = g_esrc[j];
        float w = g_ew2[j];
        if (active) acc = fmaf(w, g_h3[s * 16 + lane], acc);
    }

    int g = batch[gw];
    if (active) {
        acc = fmaf(acc, di, b3[lane]);
        atomicAdd(&g_psum[g * CCNT + lane], acc);
    }
    if (lane == 0) atomicAdd(&g_pcnt[g], 1.0f);
}

// ---------------- final: mean + log_softmax ----------------
__global__ void k_finalize(float* __restrict__ out) {
    int g = threadIdx.x;   // 128 threads
    if (g >= GCNT) return;
    float c = fmaxf(g_pcnt[g], 1.0f);
    float v[CCNT];
    float m = -1e30f;
#pragma unroll
    for (int j = 0; j < CCNT; j++) {
        v[j] = g_psum[g * CCNT + j] / c;
        m = fmaxf(m, v[j]);
    }
    float s = 0.0f;
#pragma unroll
    for (int j = 0; j < CCNT; j++) s += expf(v[j] - m);
    float lse = logf(s) + m;
#pragma unroll
    for (int j = 0; j < CCNT; j++) out[g * CCNT + j] = v[j] - lse;
}

// ---------------- launch ----------------
extern "C" void kernel_launch(void* const* d_in, const int* in_sizes, int n_in,
                              void* d_out, int out_size) {
    const float* x    = (const float*)d_in[0];
    const int*   ei   = (const int*)d_in[1];
    const float* ea   = (const float*)d_in[2];
    const int*   bat  = (const int*)d_in[3];
    const float* W1   = (const float*)d_in[4];
    const float* b1   = (const float*)d_in[5];
    const float* W2   = (const float*)d_in[6];
    const float* b2   = (const float*)d_in[7];
    const float* W3   = (const float*)d_in[8];
    const float* b3   = (const float*)d_in[9];
    float* out = (float*)d_out;

    int n = in_sizes[0] / HDIM;   // 50000
    int e = in_sizes[1] / 2;      // 800000
    const int* src = ei;
    const int* dst = ei + e;

    float *gh, *gagg;
    cudaGetSymbolAddress((void**)&gh, g_h);
    cudaGetSymbolAddress((void**)&gagg, g_agg);

    int nb = (n + SCAN_BLK - 1) / SCAN_BLK;

    // --- preprocessing: degrees + CSR-by-dst ---
    k_init<<<(n + 255) / 256, 256>>>(n);
    k_count<<<(e + 255) / 256, 256>>>(dst, ea, e);
    k_dinv<<<(n + 255) / 256, 256>>>(n);
    k_scan1<<<nb, SCAN_BLK>>>(n);
    k_scan2<<<1, 128>>>(nb, n, e);
    k_scan3<<<nb, SCAN_BLK>>>(n);
    k_scatter<<<(e + 255) / 256, 256>>>(src, dst, ea, e);

    int gemmBlocks = (n + 127) / 128;
    int aggBlocks = (n * 32 + 255) / 256;

    // layer 1: h = x@W1 ; agg + b1 ; relu
    sgemm128<<<gemmBlocks, 256>>>(x, W1, gh, n);
    agg_h128<<<aggBlocks, 256>>>(gh, gagg, b1, 1, n);

    // layer 2
    sgemm128<<<gemmBlocks, 256>>>(gagg, W2, gh, n);
    agg_h128<<<aggBlocks, 256>>>(gh, gagg, b2, 1, n);

    // layer 3: project to C first (12.8x less edge traffic), then aggregate + pool
    gemm_w3<<<(n + 31) / 32, 512>>>(gagg, W3, n);
    agg_c16_pool<<<aggBlocks, 256>>>(bat, b3, n);

    k_finalize<<<1, 128>>>(out);
}

// round 4
// speedup vs baseline: 1.5997x; 1.2260x over previous
#include <cuda_runtime.h>
#include <cuda_bf16.h>
#include <math.h>

// Problem constants
#define NMAX 50000
#define EMAX 800000
#define HDIM 128
#define GCNT 128
#define CCNT 10
#define SCAN_BLK 512

// ---------------- device scratch (no cudaMalloc allowed) ----------------
__device__ float g_h[NMAX * HDIM];     // GEMM output / agg input
__device__ float g_agg[NMAX * HDIM];   // aggregated features (next layer input)
__device__ float g_h3[NMAX * 16];      // layer-3 projected features (padded C)
__device__ float g_deg[NMAX];
__device__ float g_dinv[NMAX];
__device__ int   g_cnt[NMAX];
__device__ int   g_row[NMAX + 1];
__device__ int   g_cur[NMAX];
__device__ int   g_bsum[128];
__device__ int   g_boff[128];
__device__ int   g_esrc[EMAX];
__device__ float g_ew2[EMAX];          // ew * dinv[src]
__device__ float g_psum[GCNT * CCNT];
__device__ float g_pcnt[GCNT];

// ---------------- preprocessing ----------------

__global__ void k_init(int n) {
    int i = blockIdx.x * blockDim.x + threadIdx.x;
    if (i < n) { g_deg[i] = 1.0f; g_cnt[i] = 0; }   // self-loop weight 1
    if (i < GCNT * CCNT) g_psum[i] = 0.0f;
    if (i < GCNT) g_pcnt[i] = 0.0f;
}

__global__ void k_count(const int* __restrict__ dst, const float* __restrict__ ew, int e) {
    int i = blockIdx.x * blockDim.x + threadIdx.x;
    if (i >= e) return;
    int d = dst[i];
    atomicAdd(&g_deg[d], ew[i]);
    atomicAdd(&g_cnt[d], 1);
}

__global__ void k_dinv(int n) {
    int i = blockIdx.x * blockDim.x + threadIdx.x;
    if (i >= n) return;
    float d = g_deg[i];
    g_dinv[i] = (d > 0.0f) ? rsqrtf(d) : 0.0f;
}

// ---- multi-block exclusive scan of g_cnt -> g_row (3 phases) ----

__global__ void k_scan1(int n) {
    __shared__ int sd[SCAN_BLK];
    int tid = threadIdx.x;
    int i = blockIdx.x * SCAN_BLK + tid;
    int v = (i < n) ? g_cnt[i] : 0;
    sd[tid] = v;
    __syncthreads();
#pragma unroll
    for (int off = 1; off < SCAN_BLK; off <<= 1) {
        int t = (tid >= off) ? sd[tid - off] : 0;
        __syncthreads();
        sd[tid] += t;
        __syncthreads();
    }
    if (i < n) g_row[i] = sd[tid] - v;
    if (tid == SCAN_BLK - 1) g_bsum[blockIdx.x] = sd[SCAN_BLK - 1];
}

__global__ void k_scan2(int nb, int n, int e) {
    __shared__ int sd[128];
    int tid = threadIdx.x;
    int v = (tid < nb) ? g_bsum[tid] : 0;
    sd[tid] = v;
    __syncthreads();
#pragma unroll
    for (int off = 1; off < 128; off <<= 1) {
        int t = (tid >= off) ? sd[tid - off] : 0;
        __syncthreads();
        sd[tid] += t;
        __syncthreads();
    }
    if (tid < nb) g_boff[tid] = sd[tid] - v;
    if (tid == 0) g_row[n] = e;
}

__global__ void k_scan3(int n) {
    int i = blockIdx.x * SCAN_BLK + threadIdx.x;
    if (i < n) {
        int r = g_row[i] + g_boff[blockIdx.x];
        g_row[i] = r;
        g_cur[i] = r;
    }
}

__global__ void k_scatter(const int* __restrict__ src, const int* __restrict__ dst,
                          const float* __restrict__ ew, int e) {
    int i = blockIdx.x * blockDim.x + threadIdx.x;
    if (i >= e) return;
    int s = src[i], d = dst[i];
    int pos = atomicAdd(&g_cur[d], 1);
    g_esrc[pos] = s;
    g_ew2[pos] = ew[i] * g_dinv[s];
}

// ---------------- tensor-core GEMM (3xTF32): [M,128] @ [128,128] -> [M,128] ----
// BM=128 BN=128 BK=16, 256 threads = 8 warps; warp w owns rows w*16..w*16+15.
// mma.sync.m16n8k8 tf32 with hi/lo split: C = Ah*Bh + Ah*Bl + Al*Bh (near-fp32).

#define TF32_MASK 0xFFFFE000u

__device__ __forceinline__ void mma_tf32(float* c, const unsigned* a,
                                         unsigned b0, unsigned b1) {
    asm volatile(
        "mma.sync.aligned.m16n8k8.row.col.f32.tf32.tf32.f32 "
        "{%0,%1,%2,%3}, {%4,%5,%6,%7}, {%8,%9}, {%0,%1,%2,%3};\n"
        : "+f"(c[0]), "+f"(c[1]), "+f"(c[2]), "+f"(c[3])
        : "r"(a[0]), "r"(a[1]), "r"(a[2]), "r"(a[3]), "r"(b0), "r"(b1));
}

__global__ __launch_bounds__(256, 2)
void sgemm128_tf32(const float* __restrict__ A, const float* __restrict__ B,
                   float* __restrict__ C, int M) {
    // A tile [row 0..127][k 0..15], stride 20 -> conflict-free frag reads
    // B tile [k 0..15][n 0..127], stride 136 -> conflict-free frag reads
    __shared__ float As[2][128][20];
    __shared__ float Bs[2][16][136];

    int tid  = threadIdx.x;
    int warp = tid >> 5;
    int lane = tid & 31;
    int g = lane >> 2;      // 0..7
    int t = lane & 3;       // 0..3
    int r0 = warp * 16;
    int rowBase = blockIdx.x * 128;

    // loader mapping
    int aRow = tid >> 1;          // 0..127
    int aOff = (tid & 1) * 8;     // 0 or 8
    int bRow = tid >> 4;          // 0..15
    int bOff = (tid & 15) * 8;    // 0..120

    bool aOk = (rowBase + aRow) < M;
    const float* Ap = A + (size_t)(aOk ? rowBase + aRow : 0) * 128;

    float acc[16][4];
#pragma unroll
    for (int j = 0; j < 16; j++)
#pragma unroll
        for (int q = 0; q < 4; q++) acc[j][q] = 0.0f;

    // preload stage 0
    {
        float4 z = make_float4(0.f, 0.f, 0.f, 0.f);
        float4 a0 = aOk ? *(const float4*)(Ap + aOff)     : z;
        float4 a1 = aOk ? *(const float4*)(Ap + aOff + 4) : z;
        *(float4*)&As[0][aRow][aOff]     = a0;
        *(float4*)&As[0][aRow][aOff + 4] = a1;
        float4 b0 = *(const float4*)(B + (size_t)bRow * 128 + bOff);
        float4 b1 = *(const float4*)(B + (size_t)bRow * 128 + bOff + 4);
        *(float4*)&Bs[0][bRow][bOff]     = b0;
        *(float4*)&Bs[0][bRow][bOff + 4] = b1;
    }
    __syncthreads();

    int p = 0;
    for (int k0 = 0; k0 < 128; k0 += 16) {
        bool more = (k0 + 16) < 128;
        float4 pa0, pa1, pb0, pb1;
        if (more) {
            float4 z = make_float4(0.f, 0.f, 0.f, 0.f);
            pa0 = aOk ? *(const float4*)(Ap + k0 + 16 + aOff)     : z;
            pa1 = aOk ? *(const float4*)(Ap + k0 + 16 + aOff + 4) : z;
            pb0 = *(const float4*)(B + (size_t)(k0 + 16 + bRow) * 128 + bOff);
            pb1 = *(const float4*)(B + (size_t)(k0 + 16 + bRow) * 128 + bOff + 4);
        }

#pragma unroll
        for (int kk = 0; kk < 16; kk += 8) {
            // A fragments (m16n8k8 row-major): rows g,g+8 ; cols t,t+4
            float av0 = As[p][r0 + g    ][kk + t];
            float av1 = As[p][r0 + g + 8][kk + t];
            float av2 = As[p][r0 + g    ][kk + t + 4];
            float av3 = As[p][r0 + g + 8][kk + t + 4];
            unsigned ahi[4], alo[4];
            {
                float av[4] = {av0, av1, av2, av3};
#pragma unroll
                for (int q = 0; q < 4; q++) {
                    unsigned h = __float_as_uint(av[q]) & TF32_MASK;
                    ahi[q] = h;
                    alo[q] = __float_as_uint(av[q] - __uint_as_float(h));
                }
            }
#pragma unroll
            for (int j = 0; j < 16; j++) {
                // B fragment (col-major 8x8): k = t, t+4 ; n = j*8 + g
                float bv0 = Bs[p][kk + t    ][j * 8 + g];
                float bv1 = Bs[p][kk + t + 4][j * 8 + g];
                unsigned bh0 = __float_as_uint(bv0) & TF32_MASK;
                unsigned bh1 = __float_as_uint(bv1) & TF32_MASK;
                unsigned bl0 = __float_as_uint(bv0 - __uint_as_float(bh0));
                unsigned bl1 = __float_as_uint(bv1 - __uint_as_float(bh1));
                mma_tf32(acc[j], ahi, bh0, bh1);   // hi*hi
                mma_tf32(acc[j], ahi, bl0, bl1);   // hi*lo
                mma_tf32(acc[j], alo, bh0, bh1);   // lo*hi
            }
        }

        if (more) {
            int q = p ^ 1;
            *(float4*)&As[q][aRow][aOff]     = pa0;
            *(float4*)&As[q][aRow][aOff + 4] = pa1;
            *(float4*)&Bs[q][bRow][bOff]     = pb0;
            *(float4*)&Bs[q][bRow][bOff + 4] = pb1;
            __syncthreads();
            p = q;
        }
    }

    // epilogue: c0,c1 -> (row g, cols 2t,2t+1); c2,c3 -> (row g+8)
    int rA = rowBase + r0 + g;
    int rB = rA + 8;
#pragma unroll
    for (int j = 0; j < 16; j++) {
        int col = j * 8 + 2 * t;
        if (rA < M) *(float2*)(C + (size_t)rA * 128 + col) = make_float2(acc[j][0], acc[j][1]);
        if (rB < M) *(float2*)(C + (size_t)rB * 128 + col) = make_float2(acc[j][2], acc[j][3]);
    }
}

// ---------------- aggregation: out[i] = dinv[i]*(sum_e w'_e h[src] + dinv[i] h[i]) + b ----------------
__global__ __launch_bounds__(256)
void agg_h128(const float* __restrict__ h, float* __restrict__ out,
              const float* __restrict__ bias, int do_relu, int n) {
    int gw = (blockIdx.x * blockDim.x + threadIdx.x) >> 5;
    if (gw >= n) return;
    int lane = threadIdx.x & 31;
    const float4* h4 = (const float4*)h;

    float di = g_dinv[gw];
    float4 acc = h4[gw * 32 + lane];
    acc.x *= di; acc.y *= di; acc.z *= di; acc.w *= di;

    int j = g_row[gw];
    int end = g_row[gw + 1];
    for (; j + 4 <= end; j += 4) {
        int s0 = g_esrc[j], s1 = g_esrc[j + 1], s2 = g_esrc[j + 2], s3 = g_esrc[j + 3];
        float w0 = g_ew2[j], w1 = g_ew2[j + 1], w2 = g_ew2[j + 2], w3 = g_ew2[j + 3];
        float4 v0 = h4[s0 * 32 + lane];
        float4 v1 = h4[s1 * 32 + lane];
        float4 v2 = h4[s2 * 32 + lane];
        float4 v3 = h4[s3 * 32 + lane];
        acc.x = fmaf(w0, v0.x, acc.x); acc.y = fmaf(w0, v0.y, acc.y);
        acc.z = fmaf(w0, v0.z, acc.z); acc.w = fmaf(w0, v0.w, acc.w);
        acc.x = fmaf(w1, v1.x, acc.x); acc.y = fmaf(w1, v1.y, acc.y);
        acc.z = fmaf(w1, v1.z, acc.z); acc.w = fmaf(w1, v1.w, acc.w);
        acc.x = fmaf(w2, v2.x, acc.x); acc.y = fmaf(w2, v2.y, acc.y);
        acc.z = fmaf(w2, v2.z, acc.z); acc.w = fmaf(w2, v2.w, acc.w);
        acc.x = fmaf(w3, v3.x, acc.x); acc.y = fmaf(w3, v3.y, acc.y);
        acc.z = fmaf(w3, v3.z, acc.z); acc.w = fmaf(w3, v3.w, acc.w);
    }
    for (; j < end; j++) {
        int s = g_esrc[j];
        float w = g_ew2[j];
        float4 v = h4[s * 32 + lane];
        acc.x = fmaf(w, v.x, acc.x); acc.y = fmaf(w, v.y, acc.y);
        acc.z = fmaf(w, v.z, acc.z); acc.w = fmaf(w, v.w, acc.w);
    }

    float4 bb = ((const float4*)bias)[lane];
    acc.x = fmaf(acc.x, di, bb.x);
    acc.y = fmaf(acc.y, di, bb.y);
    acc.z = fmaf(acc.z, di, bb.z);
    acc.w = fmaf(acc.w, di, bb.w);
    if (do_relu) {
        acc.x = fmaxf(acc.x, 0.f); acc.y = fmaxf(acc.y, 0.f);
        acc.z = fmaxf(acc.z, 0.f); acc.w = fmaxf(acc.w, 0.f);
    }
    ((float4*)out)[gw * 32 + lane] = acc;
}

// ---------------- layer 3 projection: [M,128] @ [128,10] -> [M,16] padded ----------------
__global__ __launch_bounds__(512)
void gemm_w3(const float* __restrict__ A, const float* __restrict__ W, int M) {
    __shared__ float xs[32][128];
    __shared__ float Ws[128 * CCNT];
    int tid = threadIdx.x;
    int r0 = blockIdx.x * 32;

    for (int t = tid; t < 1024; t += 512) {
        int r = t >> 5;
        int c4 = (t & 31) << 2;
        int grow = r0 + r;
        float4 v = make_float4(0.f, 0.f, 0.f, 0.f);
        if (grow < M) v = *(const float4*)(A + (size_t)grow * 128 + c4);
        *(float4*)&xs[r][c4] = v;
    }
    for (int t = tid; t < 128 * CCNT; t += 512) Ws[t] = W[t];
    __syncthreads();

    int r = tid >> 4;
    int c = tid & 15;
    if (c < CCNT) {
        float acc = 0.0f;
#pragma unroll
        for (int k = 0; k < 128; k++)
            acc = fmaf(xs[r][k], Ws[k * CCNT + c], acc);
        int grow = r0 + r;
        if (grow < M) g_h3[grow * 16 + c] = acc;
    }
}

// ---------------- layer 3 aggregation + global mean pool (fused) ----------------
__global__ __launch_bounds__(256)
void agg_c16_pool(const int* __restrict__ batch, const float* __restrict__ b3, int n) {
    int gw = (blockIdx.x * blockDim.x + threadIdx.x) >> 5;
    if (gw >= n) return;
    int lane = threadIdx.x & 31;
    bool active = (lane < CCNT);

    float di = g_dinv[gw];
    float acc = 0.0f;
    if (active) acc = g_h3[gw * 16 + lane] * di;

    int j = g_row[gw];
    int end = g_row[gw + 1];
    for (; j + 4 <= end; j += 4) {
        int s0 = g_esrc[j], s1 = g_esrc[j + 1], s2 = g_esrc[j + 2], s3 = g_esrc[j + 3];
        float w0 = g_ew2[j], w1 = g_ew2[j + 1], w2 = g_ew2[j + 2], w3 = g_ew2[j + 3];
        if (active) {
            acc = fmaf(w0, g_h3[s0 * 16 + lane], acc);
            acc = fmaf(w1, g_h3[s1 * 16 + lane], acc);
            acc = fmaf(w2, g_h3[s2 * 16 + lane], acc);
            acc = fmaf(w3, g_h3[s3 * 16 + lane], acc);
        }
    }
    for (; j < end; j++) {
        int s = g_esrc[j];
        float w = g_ew2[j];
        if (active) acc = fmaf(w, g_h3[s * 16 + lane], acc);
    }

    int g = batch[gw];
    if (active) {
        acc = fmaf(acc, di, b3[lane]);
        atomicAdd(&g_psum[g * CCNT + lane], acc);
    }
    if (lane == 0) atomicAdd(&g_pcnt[g], 1.0f);
}

// ---------------- final: mean + log_softmax ----------------
__global__ void k_finalize(float* __restrict__ out) {
    int g = threadIdx.x;
    if (g >= GCNT) return;
    float c = fmaxf(g_pcnt[g], 1.0f);
    float v[CCNT];
    float m = -1e30f;
#pragma unroll
    for (int j = 0; j < CCNT; j++) {
        v[j] = g_psum[g * CCNT + j] / c;
        m = fmaxf(m, v[j]);
    }
    float s = 0.0f;
#pragma unroll
    for (int j = 0; j < CCNT; j++) s += expf(v[j] - m);
    float lse = logf(s) + m;
#pragma unroll
    for (int j = 0; j < CCNT; j++) out[g * CCNT + j] = v[j] - lse;
}

// ---------------- launch ----------------
extern "C" void kernel_launch(void* const* d_in, const int* in_sizes, int n_in,
                              void* d_out, int out_size) {
    const float* x    = (const float*)d_in[0];
    const int*   ei   = (const int*)d_in[1];
    const float* ea   = (const float*)d_in[2];
    const int*   bat  = (const int*)d_in[3];
    const float* W1   = (const float*)d_in[4];
    const float* b1   = (const float*)d_in[5];
    const float* W2   = (const float*)d_in[6];
    const float* b2   = (const float*)d_in[7];
    const float* W3   = (const float*)d_in[8];
    const float* b3   = (const float*)d_in[9];
    float* out = (float*)d_out;

    int n = in_sizes[0] / HDIM;   // 50000
    int e = in_sizes[1] / 2;      // 800000
    const int* src = ei;
    const int* dst = ei + e;

    float *gh, *gagg;
    cudaGetSymbolAddress((void**)&gh, g_h);
    cudaGetSymbolAddress((void**)&gagg, g_agg);

    int nb = (n + SCAN_BLK - 1) / SCAN_BLK;

    // --- preprocessing: degrees + CSR-by-dst ---
    k_init<<<(n + 255) / 256, 256>>>(n);
    k_count<<<(e + 255) / 256, 256>>>(dst, ea, e);
    k_dinv<<<(n + 255) / 256, 256>>>(n);
    k_scan1<<<nb, SCAN_BLK>>>(n);
    k_scan2<<<1, 128>>>(nb, n, e);
    k_scan3<<<nb, SCAN_BLK>>>(n);
    k_scatter<<<(e + 255) / 256, 256>>>(src, dst, ea, e);

    int gemmBlocks = (n + 127) / 128;
    int aggBlocks = (n * 32 + 255) / 256;

    // layer 1: h = x@W1 ; agg + b1 ; relu
    sgemm128_tf32<<<gemmBlocks, 256>>>(x, W1, gh, n);
    agg_h128<<<aggBlocks, 256>>>(gh, gagg, b1, 1, n);

    // layer 2
    sgemm128_tf32<<<gemmBlocks, 256>>>(gagg, W2, gh, n);
    agg_h128<<<aggBlocks, 256>>>(gh, gagg, b2, 1, n);

    // layer 3: project to C first (12.8x less edge traffic), then aggregate + pool
    gemm_w3<<<(n + 31) / 32, 512>>>(gagg, W3, n);
    agg_c16_pool<<<aggBlocks, 256>>>(bat, b3, n);

    k_finalize<<<1, 128>>>(out);
}